// round 4
// baseline (speedup 1.0000x reference)
#include <cuda_runtime.h>

#define NN 50000
#define NE 800000
#define NR 8

// ---------------- scratch (device globals; no allocs allowed) ----------------
__device__ __align__(16) float g_xw[(size_t)NN * NR * 256];   // per-rel transforms
__device__ __align__(16) float g_sd[NN * 64];                 // attention dots: s cols [0,RH), d cols [RH,2RH)
__device__ __align__(16) float g_alpha[NE * 4];               // per-edge logits -> exp
__device__ __align__(16) float g_amax[NN * 4];
__device__ __align__(16) float g_asum[NN * 4];
__device__ __align__(16) float g_accum[(size_t)NN * 256];     // aggregation output
__device__ __align__(16) float g_h[(size_t)NN * 256];         // layer activations
__device__ __align__(16) float g_ws[256 * 64];                // folded attention weights [K][64]

__device__ __forceinline__ float4 ld4(const float* p) { return *reinterpret_cast<const float4*>(p); }
__device__ __forceinline__ void st4(float* p, float4 v) { *reinterpret_cast<float4*>(p) = v; }

__device__ __forceinline__ void atomicMaxFloat(float* addr, float v) {
    if (v >= 0.f) atomicMax(reinterpret_cast<int*>(addr), __float_as_int(v));
    else atomicMin(reinterpret_cast<unsigned int*>(addr), (unsigned int)__float_as_int(v));
}

// ---------------- ws[k][col] = sum_c W[r][k][h*C+c] * a_{src|dst}[h][c] ----------------
template<int H, int C>
__global__ void prep_ws_kernel(const float* __restrict__ W, const float* __restrict__ a_src,
                               const float* __restrict__ a_dst, int K) {
    int idx = blockIdx.x * blockDim.x + threadIdx.x;
    if (idx >= K * 64) return;
    int k = idx >> 6;
    int col = idx & 63;
    constexpr int RH = NR * H;
    float acc = 0.f;
    if (col < 2 * RH) {
        int isd = col >= RH;
        int rh = isd ? col - RH : col;
        int r = rh / H, h = rh % H;
        const float* a = isd ? a_dst : a_src;
        const float* wrow = W + ((size_t)r * K + k) * (H * C) + h * C;
        #pragma unroll 8
        for (int c = 0; c < C; c++) acc += wrow[c] * a[h * C + c];
    }
    g_ws[idx] = acc;
}

// ---------------- SGEMM: Y[row, z*M + col] = X[row,:] @ Wall[z][:, col] ----------------
// Template selectors avoid ANY host-side symbol-address lookups:
//   XH : 0 = use Xp param, 1 = use g_h
//   WWS: 0 = use Wp param, 1 = use g_ws
//   YSD: 0 = write g_xw,   1 = write g_sd
template<int BN, int XH, int WWS, int YSD>
__global__ void __launch_bounds__(256) gemm_kernel(const float* __restrict__ Xp,
                                                   const float* __restrict__ Wp,
                                                   int K, int M, int ldY) {
    constexpr int BM = 128, BK = 16;
    constexpr int TN = BN / 16;
    const float* X = XH ? (const float*)g_h : Xp;
    const float* Wall = WWS ? (const float*)g_ws : Wp;
    float* Y = YSD ? (float*)g_sd : (float*)g_xw;
    const float* W = Wall + (size_t)blockIdx.z * K * M;
    __shared__ float As[BK][BM];
    __shared__ float Bs[BK][BN];
    const int tid = threadIdx.x;
    const int tx = tid & 15, ty = tid >> 4;
    const int rowBase = blockIdx.x * BM;
    const int colOutBase = blockIdx.y * BN + blockIdx.z * M;

    float acc[8][TN];
    #pragma unroll
    for (int i = 0; i < 8; i++)
        #pragma unroll
        for (int j = 0; j < TN; j++) acc[i][j] = 0.f;

    for (int k0 = 0; k0 < K; k0 += BK) {
        // A tile: 128x16 floats = 512 float4, 2 per thread (transposed into As[k][m])
        #pragma unroll
        for (int i = 0; i < 2; i++) {
            int idx = tid + i * 256;
            int ar = idx >> 2;
            int ac = (idx & 3) << 2;
            int gr = rowBase + ar;
            float4 v = make_float4(0.f, 0.f, 0.f, 0.f);
            if (gr < NN) v = ld4(X + (size_t)gr * K + k0 + ac);
            As[ac + 0][ar] = v.x; As[ac + 1][ar] = v.y;
            As[ac + 2][ar] = v.z; As[ac + 3][ar] = v.w;
        }
        // B tile: 16 x BN
        #pragma unroll
        for (int i = 0; i < (BK * BN / 4) / 256; i++) {
            int idx = tid + i * 256;
            int br = idx / (BN / 4);
            int bc = (idx % (BN / 4)) << 2;
            st4(&Bs[br][bc], ld4(W + (size_t)(k0 + br) * M + blockIdx.y * BN + bc));
        }
        __syncthreads();
        #pragma unroll
        for (int kk = 0; kk < BK; kk++) {
            float av[8], bv[TN];
            float4 a0 = *reinterpret_cast<const float4*>(&As[kk][ty * 4]);
            float4 a1 = *reinterpret_cast<const float4*>(&As[kk][64 + ty * 4]);
            av[0] = a0.x; av[1] = a0.y; av[2] = a0.z; av[3] = a0.w;
            av[4] = a1.x; av[5] = a1.y; av[6] = a1.z; av[7] = a1.w;
            float4 b0 = *reinterpret_cast<const float4*>(&Bs[kk][tx * 4]);
            bv[0] = b0.x; bv[1] = b0.y; bv[2] = b0.z; bv[3] = b0.w;
            if constexpr (TN == 8) {
                float4 b1 = *reinterpret_cast<const float4*>(&Bs[kk][64 + tx * 4]);
                bv[4] = b1.x; bv[5] = b1.y; bv[6] = b1.z; bv[7] = b1.w;
            }
            #pragma unroll
            for (int i = 0; i < 8; i++)
                #pragma unroll
                for (int j = 0; j < TN; j++) acc[i][j] = fmaf(av[i], bv[j], acc[i][j]);
        }
        __syncthreads();
    }
    #pragma unroll
    for (int i = 0; i < 8; i++) {
        int lr = (i < 4) ? (ty * 4 + i) : (64 + ty * 4 + (i - 4));
        int gr = rowBase + lr;
        if (gr >= NN) continue;
        float* yp = Y + (size_t)gr * ldY + colOutBase;
        st4(yp + tx * 4, make_float4(acc[i][0], acc[i][1], acc[i][2], acc[i][3]));
        if constexpr (TN == 8)
            st4(yp + 64 + tx * 4, make_float4(acc[i][4], acc[i][5], acc[i][6], acc[i][7]));
    }
}

// ---------------- init / zero ----------------
template<int H>
__global__ void init_softmax_kernel() {
    int i = blockIdx.x * blockDim.x + threadIdx.x;
    if (i < NN * H) {
        g_amax[i] = __int_as_float(0xff800000);  // -inf
        g_asum[i] = 0.f;
    }
}

__global__ void zero_accum_kernel(int n4) {
    int i = blockIdx.x * blockDim.x + threadIdx.x;
    if (i < n4) st4(reinterpret_cast<float*>(g_accum) + (size_t)i * 4, make_float4(0.f, 0.f, 0.f, 0.f));
}

// ---------------- edge logits + segment max (indices are int32: JAX x64 is disabled) ----------------
template<int H>
__global__ void edge_alpha_kernel(const int* __restrict__ ei,
                                  const int* __restrict__ et,
                                  const float* __restrict__ arel) {
    int e = blockIdx.x * blockDim.x + threadIdx.x;
    if (e >= NE) return;
    int src = ei[e], dst = ei[NE + e], r = et[e];
    if constexpr (H == 4) {
        float4 s = ld4(g_sd + src * 64 + r * 4);
        float4 d = ld4(g_sd + dst * 64 + 32 + r * 4);
        float4 a = ld4(arel + r * 4);
        float4 v;
        v.x = s.x + d.x + a.x; v.y = s.y + d.y + a.y;
        v.z = s.z + d.z + a.z; v.w = s.w + d.w + a.w;
        v.x = v.x > 0.f ? v.x : 0.2f * v.x;
        v.y = v.y > 0.f ? v.y : 0.2f * v.y;
        v.z = v.z > 0.f ? v.z : 0.2f * v.z;
        v.w = v.w > 0.f ? v.w : 0.2f * v.w;
        st4(g_alpha + (size_t)e * 4, v);
        atomicMaxFloat(&g_amax[dst * 4 + 0], v.x);
        atomicMaxFloat(&g_amax[dst * 4 + 1], v.y);
        atomicMaxFloat(&g_amax[dst * 4 + 2], v.z);
        atomicMaxFloat(&g_amax[dst * 4 + 3], v.w);
    } else {
        float v = g_sd[src * 64 + r] + g_sd[dst * 64 + 8 + r] + arel[r];
        v = v > 0.f ? v : 0.2f * v;
        g_alpha[e] = v;
        atomicMaxFloat(&g_amax[dst], v);
    }
}

// ---------------- exp + segment sum ----------------
template<int H>
__global__ void edge_exp_kernel(const int* __restrict__ ei) {
    int e = blockIdx.x * blockDim.x + threadIdx.x;
    if (e >= NE) return;
    int dst = ei[NE + e];
    if constexpr (H == 4) {
        float4 v = ld4(g_alpha + (size_t)e * 4);
        float4 m = ld4(g_amax + dst * 4);
        float4 ex = make_float4(expf(v.x - m.x), expf(v.y - m.y), expf(v.z - m.z), expf(v.w - m.w));
        st4(g_alpha + (size_t)e * 4, ex);
        atomicAdd(reinterpret_cast<float4*>(g_asum + dst * 4), ex);
    } else {
        float ex = expf(g_alpha[e] - g_amax[dst]);
        g_alpha[e] = ex;
        atomicAdd(&g_asum[dst], ex);
    }
}

// ---------------- weighted message aggregation (warp per edge) ----------------
template<int M, int H>
__global__ void agg_kernel(const int* __restrict__ ei, const int* __restrict__ et) {
    int gw = (blockIdx.x * blockDim.x + threadIdx.x) >> 5;
    int lane = threadIdx.x & 31;
    if (gw >= NE) return;
    int src = ei[gw], dst = ei[NE + gw], r = et[gw];
    const float* xp = g_xw + ((size_t)src * NR + r) * M;
    float* op = g_accum + (size_t)dst * M;
    if constexpr (H == 4) {
        float4 ex = ld4(g_alpha + (size_t)gw * 4);
        float4 den = ld4(g_asum + dst * 4);
        float w0 = ex.x / den.x, w1 = ex.y / den.y, w2 = ex.z / den.z, w3 = ex.w / den.w;
        float sA = (lane < 16) ? w0 : w1;   // first 128 ch = heads 0,1
        float sB = (lane < 16) ? w2 : w3;   // last 128 ch = heads 2,3
        float4 v0 = ld4(xp + lane * 4);
        float4 v1 = ld4(xp + 128 + lane * 4);
        v0.x *= sA; v0.y *= sA; v0.z *= sA; v0.w *= sA;
        v1.x *= sB; v1.y *= sB; v1.z *= sB; v1.w *= sB;
        atomicAdd(reinterpret_cast<float4*>(op + lane * 4), v0);
        atomicAdd(reinterpret_cast<float4*>(op + 128 + lane * 4), v1);
    } else {
        float w = g_alpha[gw] / g_asum[dst];
        if (lane < 16) {
            float4 v = ld4(xp + lane * 4);
            v.x *= w; v.y *= w; v.z *= w; v.w *= w;
            atomicAdd(reinterpret_cast<float4*>(op + lane * 4), v);
        }
    }
}

// ---------------- bias + layernorm + elu (warp per node, 256 ch) ----------------
__global__ void ln_elu_kernel(const float* __restrict__ bias, const float* __restrict__ gam,
                              const float* __restrict__ bet) {
    int n = (blockIdx.x * blockDim.x + threadIdx.x) >> 5;
    int lane = threadIdx.x & 31;
    if (n >= NN) return;
    const float* ap = g_accum + (size_t)n * 256;
    int c0 = lane * 4, c1 = 128 + lane * 4;
    float4 x0 = ld4(ap + c0), x1 = ld4(ap + c1);
    float4 b0 = ld4(bias + c0), b1 = ld4(bias + c1);
    x0.x += b0.x; x0.y += b0.y; x0.z += b0.z; x0.w += b0.w;
    x1.x += b1.x; x1.y += b1.y; x1.z += b1.z; x1.w += b1.w;
    float sum = x0.x + x0.y + x0.z + x0.w + x1.x + x1.y + x1.z + x1.w;
    float sq = x0.x * x0.x + x0.y * x0.y + x0.z * x0.z + x0.w * x0.w
             + x1.x * x1.x + x1.y * x1.y + x1.z * x1.z + x1.w * x1.w;
    #pragma unroll
    for (int o = 16; o; o >>= 1) {
        sum += __shfl_xor_sync(0xffffffffu, sum, o);
        sq  += __shfl_xor_sync(0xffffffffu, sq, o);
    }
    float mean = sum * (1.f / 256.f);
    float var = sq * (1.f / 256.f) - mean * mean;
    float rstd = rsqrtf(var + 1e-5f);
    float4 g0 = ld4(gam + c0), g1 = ld4(gam + c1);
    float4 e0 = ld4(bet + c0), e1 = ld4(bet + c1);
    float4 y0, y1;
    y0.x = (x0.x - mean) * rstd * g0.x + e0.x;
    y0.y = (x0.y - mean) * rstd * g0.y + e0.y;
    y0.z = (x0.z - mean) * rstd * g0.z + e0.z;
    y0.w = (x0.w - mean) * rstd * g0.w + e0.w;
    y1.x = (x1.x - mean) * rstd * g1.x + e1.x;
    y1.y = (x1.y - mean) * rstd * g1.y + e1.y;
    y1.z = (x1.z - mean) * rstd * g1.z + e1.z;
    y1.w = (x1.w - mean) * rstd * g1.w + e1.w;
    y0.x = y0.x > 0.f ? y0.x : expm1f(y0.x);
    y0.y = y0.y > 0.f ? y0.y : expm1f(y0.y);
    y0.z = y0.z > 0.f ? y0.z : expm1f(y0.z);
    y0.w = y0.w > 0.f ? y0.w : expm1f(y0.w);
    y1.x = y1.x > 0.f ? y1.x : expm1f(y1.x);
    y1.y = y1.y > 0.f ? y1.y : expm1f(y1.y);
    y1.z = y1.z > 0.f ? y1.z : expm1f(y1.z);
    y1.w = y1.w > 0.f ? y1.w : expm1f(y1.w);
    float* hp = g_h + (size_t)n * 256;
    st4(hp + c0, y0);
    st4(hp + c1, y1);
}

__global__ void final_bias_kernel(const float* __restrict__ bi, float* __restrict__ out) {
    int i = blockIdx.x * blockDim.x + threadIdx.x;
    if (i < NN * 64) out[i] = g_accum[i] + bi[i & 63];
}

// ---------------- orchestration (kernel launches ONLY — graph-capture-safe) ----------------
extern "C" void kernel_launch(void* const* d_in, const int* in_sizes, int n_in,
                              void* d_out, int out_size) {
    (void)in_sizes; (void)n_in; (void)out_size;
    const float* x  = (const float*)d_in[0];
    const int* ei   = (const int*)d_in[1];   // int32: JAX default (x64 disabled)
    const int* et   = (const int*)d_in[2];
    const float* W0 = (const float*)d_in[3];
    const float* as0 = (const float*)d_in[4];
    const float* ad0 = (const float*)d_in[5];
    const float* ar0 = (const float*)d_in[6];
    const float* bi0 = (const float*)d_in[7];
    const float* W1 = (const float*)d_in[8];
    const float* as1 = (const float*)d_in[9];
    const float* ad1 = (const float*)d_in[10];
    const float* ar1 = (const float*)d_in[11];
    const float* bi1 = (const float*)d_in[12];
    const float* W2 = (const float*)d_in[13];
    const float* as2 = (const float*)d_in[14];
    const float* ad2 = (const float*)d_in[15];
    const float* ar2 = (const float*)d_in[16];
    const float* bi2 = (const float*)d_in[17];
    const float* g0 = (const float*)d_in[18];
    const float* be0 = (const float*)d_in[19];
    const float* g1 = (const float*)d_in[20];
    const float* be1 = (const float*)d_in[21];
    float* out = (float*)d_out;

    const int TB = 256;
    const int NT = (NN + 127) / 128;          // 391 row tiles
    dim3 gMain(NT, 2, 8);                      // BN=128, M=256
    dim3 gL2(NT, 1, 8);                        // BN=64,  M=64
    dim3 gDots(NT, 1, 1);                      // BN=64,  M=64
    int ge = (NE + TB - 1) / TB;               // edge-thread grid
    int gw = (NE * 32 + TB - 1) / TB;          // edge-warp grid
    int gn = (NN * 32 + TB - 1) / TB;          // node-warp grid

    // ======== layer 0: in=128 -> [8 rel] x 256, H=4 ========
    prep_ws_kernel<4, 64><<<(128 * 64 + TB - 1) / TB, TB>>>(W0, as0, ad0, 128);
    gemm_kernel<64, 0, 1, 1><<<gDots, TB>>>(x, nullptr, 128, 64, 64);
    gemm_kernel<128, 0, 0, 0><<<gMain, TB>>>(x, W0, 128, 256, 2048);
    init_softmax_kernel<4><<<(NN * 4 + TB - 1) / TB, TB>>>();
    zero_accum_kernel<<<(NN * 64 + TB - 1) / TB, TB>>>(NN * 64);
    edge_alpha_kernel<4><<<ge, TB>>>(ei, et, ar0);
    edge_exp_kernel<4><<<ge, TB>>>(ei);
    agg_kernel<256, 4><<<gw, TB>>>(ei, et);
    ln_elu_kernel<<<gn, TB>>>(bi0, g0, be0);

    // ======== layer 1: in=256 -> [8 rel] x 256, H=4 ========
    prep_ws_kernel<4, 64><<<(256 * 64 + TB - 1) / TB, TB>>>(W1, as1, ad1, 256);
    gemm_kernel<64, 1, 1, 1><<<gDots, TB>>>(nullptr, nullptr, 256, 64, 64);
    gemm_kernel<128, 1, 0, 0><<<gMain, TB>>>(nullptr, W1, 256, 256, 2048);
    init_softmax_kernel<4><<<(NN * 4 + TB - 1) / TB, TB>>>();
    zero_accum_kernel<<<(NN * 64 + TB - 1) / TB, TB>>>(NN * 64);
    edge_alpha_kernel<4><<<ge, TB>>>(ei, et, ar1);
    edge_exp_kernel<4><<<ge, TB>>>(ei);
    agg_kernel<256, 4><<<gw, TB>>>(ei, et);
    ln_elu_kernel<<<gn, TB>>>(bi1, g1, be1);

    // ======== layer 2: in=256 -> [8 rel] x 64, H=1, no concat ========
    prep_ws_kernel<1, 64><<<(256 * 64 + TB - 1) / TB, TB>>>(W2, as2, ad2, 256);
    gemm_kernel<64, 1, 1, 1><<<gDots, TB>>>(nullptr, nullptr, 256, 64, 64);
    gemm_kernel<64, 1, 0, 0><<<gL2, TB>>>(nullptr, W2, 256, 64, 512);
    init_softmax_kernel<1><<<(NN + TB - 1) / TB, TB>>>();
    zero_accum_kernel<<<(NN * 16 + TB - 1) / TB, TB>>>(NN * 16);
    edge_alpha_kernel<1><<<ge, TB>>>(ei, et, ar2);
    edge_exp_kernel<1><<<ge, TB>>>(ei);
    agg_kernel<64, 1><<<gw, TB>>>(ei, et);
    final_bias_kernel<<<(NN * 64 + TB - 1) / TB, TB>>>(bi2, out);
}

// round 6
// speedup vs baseline: 1.4540x; 1.4540x over previous
#include <cuda_runtime.h>
#include <cuda_bf16.h>
#include <cstdint>

#define NN 50000
#define NE 800000
#define NR 8

// ---------------- scratch (device globals; no allocs allowed) ----------------
__device__ __align__(16) float g_xw[(size_t)NN * NR * 256];   // per-rel transforms
__device__ __align__(16) float g_sd[NN * 64];                 // attention dots
__device__ __align__(16) float g_alpha[NE * 4];
__device__ __align__(16) float g_amax[NN * 4];
__device__ __align__(16) float g_asum[NN * 4];
__device__ __align__(16) float g_accum[(size_t)NN * 256];
__device__ __align__(16) float g_h[(size_t)NN * 256];
__device__ __align__(16) float g_ws[256 * 64];

__device__ __forceinline__ float4 ld4(const float* p) { return *reinterpret_cast<const float4*>(p); }
__device__ __forceinline__ void st4(float* p, float4 v) { *reinterpret_cast<float4*>(p) = v; }

__device__ __forceinline__ void atomicMaxFloat(float* addr, float v) {
    if (v >= 0.f) atomicMax(reinterpret_cast<int*>(addr), __float_as_int(v));
    else atomicMin(reinterpret_cast<unsigned int*>(addr), (unsigned int)__float_as_int(v));
}

__device__ __forceinline__ uint32_t smem_u32(const void* p) {
    uint32_t a;
    asm("{ .reg .u64 t; cvta.to.shared.u64 t, %1; cvt.u32.u64 %0, t; }" : "=r"(a) : "l"(p));
    return a;
}

// fp32 pair -> bf16 hi pair + bf16 lo (residual) pair, packed as u32
__device__ __forceinline__ void split2(float x, float y, unsigned& hi, unsigned& lo) {
    __nv_bfloat16 hx = __float2bfloat16(x), hy = __float2bfloat16(y);
    float rx = x - __bfloat162float(hx), ry = y - __bfloat162float(hy);
    __nv_bfloat162 h; h.x = hx; h.y = hy;
    __nv_bfloat162 l = __floats2bfloat162_rn(rx, ry);
    hi = *reinterpret_cast<unsigned*>(&h);
    lo = *reinterpret_cast<unsigned*>(&l);
}

__device__ __forceinline__ void ldsm_x4(uint32_t addr, uint32_t& r0, uint32_t& r1, uint32_t& r2, uint32_t& r3) {
    asm volatile("ldmatrix.sync.aligned.m8n8.x4.shared.b16 {%0,%1,%2,%3}, [%4];"
                 : "=r"(r0), "=r"(r1), "=r"(r2), "=r"(r3) : "r"(addr));
}
__device__ __forceinline__ void ldsm_x4t(uint32_t addr, uint32_t& r0, uint32_t& r1, uint32_t& r2, uint32_t& r3) {
    asm volatile("ldmatrix.sync.aligned.m8n8.x4.trans.shared.b16 {%0,%1,%2,%3}, [%4];"
                 : "=r"(r0), "=r"(r1), "=r"(r2), "=r"(r3) : "r"(addr));
}
__device__ __forceinline__ void mma_bf16(float* d, const uint32_t* a, uint32_t b0, uint32_t b1) {
    asm volatile("mma.sync.aligned.m16n8k16.row.col.f32.bf16.bf16.f32 "
                 "{%0,%1,%2,%3}, {%4,%5,%6,%7}, {%8,%9}, {%0,%1,%2,%3};"
                 : "+f"(d[0]), "+f"(d[1]), "+f"(d[2]), "+f"(d[3])
                 : "r"(a[0]), "r"(a[1]), "r"(a[2]), "r"(a[3]), "r"(b0), "r"(b1));
}

// ======== HMMA split-bf16 GEMM: g_xw[row, z*NCOLS + col] = X[row,:]·W[z][:,col] ========
// NCOLS per relation (256 or 64); BN = min(NCOLS,128) per block-y; KTOT reduction; XH: X = g_h.
template<int NCOLS, int KTOT, int XH>
__global__ void __launch_bounds__(256) mma_gemm(const float* __restrict__ Xp,
                                                const float* __restrict__ Wp, int ldY) {
    constexpr int BN = (NCOLS < 128) ? NCOLS : 128;
    constexpr int WN = BN / 2;          // warp n-tile (64 or 32)
    constexpr int NF2 = WN / 16;        // n16 fragments per warp (4 or 2)
    constexpr int AST = 40;             // A smem row stride (bf16 elems)
    constexpr int BST = BN + 8;         // B smem row stride

    __shared__ __align__(16) __nv_bfloat16 Ah[128][AST];
    __shared__ __align__(16) __nv_bfloat16 Al[128][AST];
    __shared__ __align__(16) __nv_bfloat16 Bh[32][BST];
    __shared__ __align__(16) __nv_bfloat16 Bl[32][BST];

    const int tid = threadIdx.x;
    const int wid = tid >> 5, lane = tid & 31;
    const int wm = wid & 3, wn = wid >> 2;       // 4 m-warps x 2 n-warps
    const int rowBase = blockIdx.x * 128;
    const int nbase = blockIdx.y * BN;
    const int z = blockIdx.z;
    const float* X = XH ? (const float*)g_h : Xp;
    const float* W = Wp + (size_t)z * KTOT * NCOLS;

    float acc[2][WN / 8][4];
    #pragma unroll
    for (int i = 0; i < 2; i++)
        #pragma unroll
        for (int j = 0; j < WN / 8; j++)
            #pragma unroll
            for (int q = 0; q < 4; q++) acc[i][j][q] = 0.f;

    for (int k0 = 0; k0 < KTOT; k0 += 32) {
        // ---- stage A: 128 rows x 32 k (fp32 -> hi/lo bf16) ----
        #pragma unroll
        for (int i = 0; i < 4; i++) {
            int li = tid + i * 256;              // 1024 float4 slots
            int row = li >> 3, c4 = li & 7;
            int gr = rowBase + row;
            float4 v = make_float4(0.f, 0.f, 0.f, 0.f);
            if (gr < NN) v = ld4(X + (size_t)gr * KTOT + k0 + c4 * 4);
            unsigned h0, l0, h1, l1;
            split2(v.x, v.y, h0, l0);
            split2(v.z, v.w, h1, l1);
            *reinterpret_cast<uint2*>(&Ah[row][c4 * 4]) = make_uint2(h0, h1);
            *reinterpret_cast<uint2*>(&Al[row][c4 * 4]) = make_uint2(l0, l1);
        }
        // ---- stage B: 32 k-rows x BN cols ----
        #pragma unroll
        for (int i = 0; i < BN / 32; i++) {
            int li = tid + i * 256;              // (32*BN/4) float4 slots
            int row = li / (BN / 4), c4 = li % (BN / 4);
            float4 v = ld4(W + (size_t)(k0 + row) * NCOLS + nbase + c4 * 4);
            unsigned h0, l0, h1, l1;
            split2(v.x, v.y, h0, l0);
            split2(v.z, v.w, h1, l1);
            *reinterpret_cast<uint2*>(&Bh[row][c4 * 4]) = make_uint2(h0, h1);
            *reinterpret_cast<uint2*>(&Bl[row][c4 * 4]) = make_uint2(l0, l1);
        }
        __syncthreads();
        // ---- compute: 2 k16 steps ----
        #pragma unroll
        for (int ks = 0; ks < 2; ks++) {
            uint32_t ah[2][4], al[2][4];
            #pragma unroll
            for (int mf = 0; mf < 2; mf++) {
                int arow = wm * 32 + mf * 16 + (lane & 15);
                int acol = ks * 16 + ((lane >> 4) << 3);
                ldsm_x4(smem_u32(&Ah[arow][acol]), ah[mf][0], ah[mf][1], ah[mf][2], ah[mf][3]);
                ldsm_x4(smem_u32(&Al[arow][acol]), al[mf][0], al[mf][1], al[mf][2], al[mf][3]);
            }
            #pragma unroll
            for (int nf2 = 0; nf2 < NF2; nf2++) {
                int brow = ks * 16 + (lane & 15);
                int bcol = wn * WN + nf2 * 16 + ((lane >> 4) << 3);
                uint32_t bh[4], bl[4];
                ldsm_x4t(smem_u32(&Bh[brow][bcol]), bh[0], bh[1], bh[2], bh[3]);
                ldsm_x4t(smem_u32(&Bl[brow][bcol]), bl[0], bl[1], bl[2], bl[3]);
                #pragma unroll
                for (int half = 0; half < 2; half++) {
                    uint32_t bH0 = bh[half * 2], bH1 = bh[half * 2 + 1];
                    uint32_t bL0 = bl[half * 2], bL1 = bl[half * 2 + 1];
                    #pragma unroll
                    for (int mf = 0; mf < 2; mf++) {
                        float* d = acc[mf][nf2 * 2 + half];
                        mma_bf16(d, ah[mf], bH0, bH1);
                        mma_bf16(d, ah[mf], bL0, bL1);
                        mma_bf16(d, al[mf], bH0, bH1);
                    }
                }
            }
        }
        __syncthreads();
    }
    // ---- epilogue: fragment -> g_xw ----
    const int colG = z * NCOLS + nbase + wn * WN + (lane & 3) * 2;
    #pragma unroll
    for (int mf = 0; mf < 2; mf++) {
        int r0 = rowBase + wm * 32 + mf * 16 + (lane >> 2);
        #pragma unroll
        for (int nf = 0; nf < WN / 8; nf++) {
            float* d = acc[mf][nf];
            int c = colG + nf * 8;
            if (r0 < NN)
                *reinterpret_cast<float2*>(g_xw + (size_t)r0 * ldY + c) = make_float2(d[0], d[1]);
            if (r0 + 8 < NN)
                *reinterpret_cast<float2*>(g_xw + (size_t)(r0 + 8) * ldY + c) = make_float2(d[2], d[3]);
        }
    }
}

// ---------------- ws[k][col] = sum_c W[r][k][h*C+c] * a_{src|dst}[h][c] ----------------
template<int H, int C>
__global__ void prep_ws_kernel(const float* __restrict__ W, const float* __restrict__ a_src,
                               const float* __restrict__ a_dst, int K) {
    int idx = blockIdx.x * blockDim.x + threadIdx.x;
    if (idx >= K * 64) return;
    int k = idx >> 6;
    int col = idx & 63;
    constexpr int RH = NR * H;
    float acc = 0.f;
    if (col < 2 * RH) {
        int isd = col >= RH;
        int rh = isd ? col - RH : col;
        int r = rh / H, h = rh % H;
        const float* a = isd ? a_dst : a_src;
        const float* wrow = W + ((size_t)r * K + k) * (H * C) + h * C;
        #pragma unroll 8
        for (int c = 0; c < C; c++) acc += wrow[c] * a[h * C + c];
    }
    g_ws[idx] = acc;
}

// ---------------- fp32 SGEMM (attention dots only): g_sd = X @ g_ws ----------------
template<int BN, int XH>
__global__ void __launch_bounds__(256) gemm_dots(const float* __restrict__ Xp, int K) {
    constexpr int BM = 128, BK = 16;
    constexpr int TN = BN / 16;
    const float* X = XH ? (const float*)g_h : Xp;
    const float* W = (const float*)g_ws;
    float* Y = (float*)g_sd;
    __shared__ float As[BK][BM];
    __shared__ float Bs[BK][BN];
    const int tid = threadIdx.x;
    const int tx = tid & 15, ty = tid >> 4;
    const int rowBase = blockIdx.x * BM;

    float acc[8][TN];
    #pragma unroll
    for (int i = 0; i < 8; i++)
        #pragma unroll
        for (int j = 0; j < TN; j++) acc[i][j] = 0.f;

    for (int k0 = 0; k0 < K; k0 += BK) {
        #pragma unroll
        for (int i = 0; i < 2; i++) {
            int idx = tid + i * 256;
            int ar = idx >> 2;
            int ac = (idx & 3) << 2;
            int gr = rowBase + ar;
            float4 v = make_float4(0.f, 0.f, 0.f, 0.f);
            if (gr < NN) v = ld4(X + (size_t)gr * K + k0 + ac);
            As[ac + 0][ar] = v.x; As[ac + 1][ar] = v.y;
            As[ac + 2][ar] = v.z; As[ac + 3][ar] = v.w;
        }
        if (tid < BK * BN / 4) {
            int br = tid / (BN / 4);
            int bc = (tid % (BN / 4)) << 2;
            st4(&Bs[br][bc], ld4(W + (size_t)(k0 + br) * 64 + bc));
        }
        __syncthreads();
        #pragma unroll
        for (int kk = 0; kk < BK; kk++) {
            float av[8], bv[TN];
            float4 a0 = *reinterpret_cast<const float4*>(&As[kk][ty * 4]);
            float4 a1 = *reinterpret_cast<const float4*>(&As[kk][64 + ty * 4]);
            av[0] = a0.x; av[1] = a0.y; av[2] = a0.z; av[3] = a0.w;
            av[4] = a1.x; av[5] = a1.y; av[6] = a1.z; av[7] = a1.w;
            float4 b0 = *reinterpret_cast<const float4*>(&Bs[kk][tx * 4]);
            bv[0] = b0.x; bv[1] = b0.y; bv[2] = b0.z; bv[3] = b0.w;
            #pragma unroll
            for (int i = 0; i < 8; i++)
                #pragma unroll
                for (int j = 0; j < TN; j++) acc[i][j] = fmaf(av[i], bv[j], acc[i][j]);
        }
        __syncthreads();
    }
    #pragma unroll
    for (int i = 0; i < 8; i++) {
        int lr = (i < 4) ? (ty * 4 + i) : (64 + ty * 4 + (i - 4));
        int gr = rowBase + lr;
        if (gr >= NN) continue;
        st4(Y + (size_t)gr * 64 + tx * 4, make_float4(acc[i][0], acc[i][1], acc[i][2], acc[i][3]));
    }
}

// ---------------- init / zero ----------------
template<int H>
__global__ void init_softmax_kernel() {
    int i = blockIdx.x * blockDim.x + threadIdx.x;
    if (i < NN * H) {
        g_amax[i] = __int_as_float(0xff800000);
        g_asum[i] = 0.f;
    }
}

__global__ void zero_accum_kernel(int n4) {
    int i = blockIdx.x * blockDim.x + threadIdx.x;
    if (i < n4) st4(reinterpret_cast<float*>(g_accum) + (size_t)i * 4, make_float4(0.f, 0.f, 0.f, 0.f));
}

// ---------------- edge logits + segment max (int32 indices) ----------------
template<int H>
__global__ void edge_alpha_kernel(const int* __restrict__ ei,
                                  const int* __restrict__ et,
                                  const float* __restrict__ arel) {
    int e = blockIdx.x * blockDim.x + threadIdx.x;
    if (e >= NE) return;
    int src = ei[e], dst = ei[NE + e], r = et[e];
    if constexpr (H == 4) {
        float4 s = ld4(g_sd + src * 64 + r * 4);
        float4 d = ld4(g_sd + dst * 64 + 32 + r * 4);
        float4 a = ld4(arel + r * 4);
        float4 v;
        v.x = s.x + d.x + a.x; v.y = s.y + d.y + a.y;
        v.z = s.z + d.z + a.z; v.w = s.w + d.w + a.w;
        v.x = v.x > 0.f ? v.x : 0.2f * v.x;
        v.y = v.y > 0.f ? v.y : 0.2f * v.y;
        v.z = v.z > 0.f ? v.z : 0.2f * v.z;
        v.w = v.w > 0.f ? v.w : 0.2f * v.w;
        st4(g_alpha + (size_t)e * 4, v);
        atomicMaxFloat(&g_amax[dst * 4 + 0], v.x);
        atomicMaxFloat(&g_amax[dst * 4 + 1], v.y);
        atomicMaxFloat(&g_amax[dst * 4 + 2], v.z);
        atomicMaxFloat(&g_amax[dst * 4 + 3], v.w);
    } else {
        float v = g_sd[src * 64 + r] + g_sd[dst * 64 + 8 + r] + arel[r];
        v = v > 0.f ? v : 0.2f * v;
        g_alpha[e] = v;
        atomicMaxFloat(&g_amax[dst], v);
    }
}

// ---------------- exp + segment sum ----------------
template<int H>
__global__ void edge_exp_kernel(const int* __restrict__ ei) {
    int e = blockIdx.x * blockDim.x + threadIdx.x;
    if (e >= NE) return;
    int dst = ei[NE + e];
    if constexpr (H == 4) {
        float4 v = ld4(g_alpha + (size_t)e * 4);
        float4 m = ld4(g_amax + dst * 4);
        float4 ex = make_float4(expf(v.x - m.x), expf(v.y - m.y), expf(v.z - m.z), expf(v.w - m.w));
        st4(g_alpha + (size_t)e * 4, ex);
        atomicAdd(reinterpret_cast<float4*>(g_asum + dst * 4), ex);
    } else {
        float ex = expf(g_alpha[e] - g_amax[dst]);
        g_alpha[e] = ex;
        atomicAdd(&g_asum[dst], ex);
    }
}

// ---------------- weighted message aggregation (warp per edge) ----------------
template<int M, int H>
__global__ void agg_kernel(const int* __restrict__ ei, const int* __restrict__ et) {
    int gw = (blockIdx.x * blockDim.x + threadIdx.x) >> 5;
    int lane = threadIdx.x & 31;
    if (gw >= NE) return;
    int src = ei[gw], dst = ei[NE + gw], r = et[gw];
    const float* xp = g_xw + ((size_t)src * NR + r) * M;
    float* op = g_accum + (size_t)dst * M;
    if constexpr (H == 4) {
        float4 ex = ld4(g_alpha + (size_t)gw * 4);
        float4 den = ld4(g_asum + dst * 4);
        float w0 = ex.x / den.x, w1 = ex.y / den.y, w2 = ex.z / den.z, w3 = ex.w / den.w;
        float sA = (lane < 16) ? w0 : w1;
        float sB = (lane < 16) ? w2 : w3;
        float4 v0 = ld4(xp + lane * 4);
        float4 v1 = ld4(xp + 128 + lane * 4);
        v0.x *= sA; v0.y *= sA; v0.z *= sA; v0.w *= sA;
        v1.x *= sB; v1.y *= sB; v1.z *= sB; v1.w *= sB;
        atomicAdd(reinterpret_cast<float4*>(op + lane * 4), v0);
        atomicAdd(reinterpret_cast<float4*>(op + 128 + lane * 4), v1);
    } else {
        float w = g_alpha[gw] / g_asum[dst];
        if (lane < 16) {
            float4 v = ld4(xp + lane * 4);
            v.x *= w; v.y *= w; v.z *= w; v.w *= w;
            atomicAdd(reinterpret_cast<float4*>(op + lane * 4), v);
        }
    }
}

// ---------------- bias + layernorm + elu (warp per node, 256 ch) ----------------
__global__ void ln_elu_kernel(const float* __restrict__ bias, const float* __restrict__ gam,
                              const float* __restrict__ bet) {
    int n = (blockIdx.x * blockDim.x + threadIdx.x) >> 5;
    int lane = threadIdx.x & 31;
    if (n >= NN) return;
    const float* ap = g_accum + (size_t)n * 256;
    int c0 = lane * 4, c1 = 128 + lane * 4;
    float4 x0 = ld4(ap + c0), x1 = ld4(ap + c1);
    float4 b0 = ld4(bias + c0), b1 = ld4(bias + c1);
    x0.x += b0.x; x0.y += b0.y; x0.z += b0.z; x0.w += b0.w;
    x1.x += b1.x; x1.y += b1.y; x1.z += b1.z; x1.w += b1.w;
    float sum = x0.x + x0.y + x0.z + x0.w + x1.x + x1.y + x1.z + x1.w;
    float sq = x0.x * x0.x + x0.y * x0.y + x0.z * x0.z + x0.w * x0.w
             + x1.x * x1.x + x1.y * x1.y + x1.z * x1.z + x1.w * x1.w;
    #pragma unroll
    for (int o = 16; o; o >>= 1) {
        sum += __shfl_xor_sync(0xffffffffu, sum, o);
        sq  += __shfl_xor_sync(0xffffffffu, sq, o);
    }
    float mean = sum * (1.f / 256.f);
    float var = sq * (1.f / 256.f) - mean * mean;
    float rstd = rsqrtf(var + 1e-5f);
    float4 g0 = ld4(gam + c0), g1 = ld4(gam + c1);
    float4 e0 = ld4(bet + c0), e1 = ld4(bet + c1);
    float4 y0, y1;
    y0.x = (x0.x - mean) * rstd * g0.x + e0.x;
    y0.y = (x0.y - mean) * rstd * g0.y + e0.y;
    y0.z = (x0.z - mean) * rstd * g0.z + e0.z;
    y0.w = (x0.w - mean) * rstd * g0.w + e0.w;
    y1.x = (x1.x - mean) * rstd * g1.x + e1.x;
    y1.y = (x1.y - mean) * rstd * g1.y + e1.y;
    y1.z = (x1.z - mean) * rstd * g1.z + e1.z;
    y1.w = (x1.w - mean) * rstd * g1.w + e1.w;
    y0.x = y0.x > 0.f ? y0.x : expm1f(y0.x);
    y0.y = y0.y > 0.f ? y0.y : expm1f(y0.y);
    y0.z = y0.z > 0.f ? y0.z : expm1f(y0.z);
    y0.w = y0.w > 0.f ? y0.w : expm1f(y0.w);
    y1.x = y1.x > 0.f ? y1.x : expm1f(y1.x);
    y1.y = y1.y > 0.f ? y1.y : expm1f(y1.y);
    y1.z = y1.z > 0.f ? y1.z : expm1f(y1.z);
    y1.w = y1.w > 0.f ? y1.w : expm1f(y1.w);
    float* hp = g_h + (size_t)n * 256;
    st4(hp + c0, y0);
    st4(hp + c1, y1);
}

__global__ void final_bias_kernel(const float* __restrict__ bi, float* __restrict__ out) {
    int i = blockIdx.x * blockDim.x + threadIdx.x;
    if (i < NN * 64) out[i] = g_accum[i] + bi[i & 63];
}

// ---------------- orchestration (pure kernel launches) ----------------
extern "C" void kernel_launch(void* const* d_in, const int* in_sizes, int n_in,
                              void* d_out, int out_size) {
    (void)in_sizes; (void)n_in; (void)out_size;
    const float* x  = (const float*)d_in[0];
    const int* ei   = (const int*)d_in[1];
    const int* et   = (const int*)d_in[2];
    const float* W0 = (const float*)d_in[3];
    const float* as0 = (const float*)d_in[4];
    const float* ad0 = (const float*)d_in[5];
    const float* ar0 = (const float*)d_in[6];
    const float* bi0 = (const float*)d_in[7];
    const float* W1 = (const float*)d_in[8];
    const float* as1 = (const float*)d_in[9];
    const float* ad1 = (const float*)d_in[10];
    const float* ar1 = (const float*)d_in[11];
    const float* bi1 = (const float*)d_in[12];
    const float* W2 = (const float*)d_in[13];
    const float* as2 = (const float*)d_in[14];
    const float* ad2 = (const float*)d_in[15];
    const float* ar2 = (const float*)d_in[16];
    const float* bi2 = (const float*)d_in[17];
    const float* g0 = (const float*)d_in[18];
    const float* be0 = (const float*)d_in[19];
    const float* g1 = (const float*)d_in[20];
    const float* be1 = (const float*)d_in[21];
    float* out = (float*)d_out;

    const int TB = 256;
    const int NT = (NN + 127) / 128;           // 391 row tiles
    dim3 gTC2(NT, 2, 8);                        // NCOLS=256 -> 2 n-tiles of 128
    dim3 gTC1(NT, 1, 8);                        // NCOLS=64 -> 1 n-tile
    int ge = (NE + TB - 1) / TB;
    int gw = (NE * 32 + TB - 1) / TB;
    int gn = (NN * 32 + TB - 1) / TB;

    // ======== layer 0: in=128 -> [8 rel] x 256, H=4 ========
    prep_ws_kernel<4, 64><<<(128 * 64 + TB - 1) / TB, TB>>>(W0, as0, ad0, 128);
    gemm_dots<64, 0><<<NT, TB>>>(x, 128);
    mma_gemm<256, 128, 0><<<gTC2, TB>>>(x, W0, 2048);
    init_softmax_kernel<4><<<(NN * 4 + TB - 1) / TB, TB>>>();
    zero_accum_kernel<<<(NN * 64 + TB - 1) / TB, TB>>>(NN * 64);
    edge_alpha_kernel<4><<<ge, TB>>>(ei, et, ar0);
    edge_exp_kernel<4><<<ge, TB>>>(ei);
    agg_kernel<256, 4><<<gw, TB>>>(ei, et);
    ln_elu_kernel<<<gn, TB>>>(bi0, g0, be0);

    // ======== layer 1: in=256 -> [8 rel] x 256, H=4 ========
    prep_ws_kernel<4, 64><<<(256 * 64 + TB - 1) / TB, TB>>>(W1, as1, ad1, 256);
    gemm_dots<64, 1><<<NT, TB>>>(nullptr, 256);
    mma_gemm<256, 256, 1><<<gTC2, TB>>>(nullptr, W1, 2048);
    init_softmax_kernel<4><<<(NN * 4 + TB - 1) / TB, TB>>>();
    zero_accum_kernel<<<(NN * 64 + TB - 1) / TB, TB>>>(NN * 64);
    edge_alpha_kernel<4><<<ge, TB>>>(ei, et, ar1);
    edge_exp_kernel<4><<<ge, TB>>>(ei);
    agg_kernel<256, 4><<<gw, TB>>>(ei, et);
    ln_elu_kernel<<<gn, TB>>>(bi1, g1, be1);

    // ======== layer 2: in=256 -> [8 rel] x 64, H=1, no concat ========
    prep_ws_kernel<1, 64><<<(256 * 64 + TB - 1) / TB, TB>>>(W2, as2, ad2, 256);
    gemm_dots<64, 1><<<NT, TB>>>(nullptr, 256);
    mma_gemm<64, 256, 1><<<gTC1, TB>>>(nullptr, W2, 512);
    init_softmax_kernel<1><<<(NN + TB - 1) / TB, TB>>>();
    zero_accum_kernel<<<(NN * 16 + TB - 1) / TB, TB>>>(NN * 16);
    edge_alpha_kernel<1><<<ge, TB>>>(ei, et, ar2);
    edge_exp_kernel<1><<<ge, TB>>>(ei);
    agg_kernel<64, 1><<<gw, TB>>>(ei, et);
    final_bias_kernel<<<(NN * 64 + TB - 1) / TB, TB>>>(bi2, out);
}

// round 7
// speedup vs baseline: 1.5818x; 1.0879x over previous
#include <cuda_runtime.h>
#include <cuda_bf16.h>
#include <cstdint>

#define NN 50000
#define NE 800000
#define NR 8

// ---------------- scratch (device globals; no allocs allowed) ----------------
__device__ __align__(16) float g_xw[(size_t)NN * NR * 256];   // per-rel transforms
__device__ __align__(16) float g_sd[NN * 64];                 // attention dots
__device__ __align__(16) float g_alpha[NE * 4];               // per-edge exp
__device__ __align__(16) float g_asum[NN * 4];
__device__ __align__(16) float g_accum[(size_t)NN * 256];
__device__ __align__(16) float g_h[(size_t)NN * 256];
__device__ __align__(16) float g_ws[256 * 64];
__device__ __align__(16) __nv_bfloat16 g_xh[(size_t)NN * 256];  // A operand hi
__device__ __align__(16) __nv_bfloat16 g_xl[(size_t)NN * 256];  // A operand lo
__device__ __align__(16) __nv_bfloat16 g_wh[NR * 256 * 256];    // B operand hi
__device__ __align__(16) __nv_bfloat16 g_wl[NR * 256 * 256];    // B operand lo

__device__ __forceinline__ float4 ld4(const float* p) { return *reinterpret_cast<const float4*>(p); }
__device__ __forceinline__ void st4(float* p, float4 v) { *reinterpret_cast<float4*>(p) = v; }

__device__ __forceinline__ uint32_t smem_u32(const void* p) {
    uint32_t a;
    asm("{ .reg .u64 t; cvta.to.shared.u64 t, %1; cvt.u32.u64 %0, t; }" : "=r"(a) : "l"(p));
    return a;
}

// fp32 pair -> bf16 hi pair + bf16 lo (residual) pair, packed as u32
__device__ __forceinline__ void split2(float x, float y, unsigned& hi, unsigned& lo) {
    __nv_bfloat16 hx = __float2bfloat16(x), hy = __float2bfloat16(y);
    float rx = x - __bfloat162float(hx), ry = y - __bfloat162float(hy);
    __nv_bfloat162 h; h.x = hx; h.y = hy;
    __nv_bfloat162 l = __floats2bfloat162_rn(rx, ry);
    hi = *reinterpret_cast<unsigned*>(&h);
    lo = *reinterpret_cast<unsigned*>(&l);
}

__device__ __forceinline__ void ldsm_x4(uint32_t addr, uint32_t& r0, uint32_t& r1, uint32_t& r2, uint32_t& r3) {
    asm volatile("ldmatrix.sync.aligned.m8n8.x4.shared.b16 {%0,%1,%2,%3}, [%4];"
                 : "=r"(r0), "=r"(r1), "=r"(r2), "=r"(r3) : "r"(addr));
}
__device__ __forceinline__ void ldsm_x4t(uint32_t addr, uint32_t& r0, uint32_t& r1, uint32_t& r2, uint32_t& r3) {
    asm volatile("ldmatrix.sync.aligned.m8n8.x4.trans.shared.b16 {%0,%1,%2,%3}, [%4];"
                 : "=r"(r0), "=r"(r1), "=r"(r2), "=r"(r3) : "r"(addr));
}
__device__ __forceinline__ void mma_bf16(float* d, const uint32_t* a, uint32_t b0, uint32_t b1) {
    asm volatile("mma.sync.aligned.m16n8k16.row.col.f32.bf16.bf16.f32 "
                 "{%0,%1,%2,%3}, {%4,%5,%6,%7}, {%8,%9}, {%0,%1,%2,%3};"
                 : "+f"(d[0]), "+f"(d[1]), "+f"(d[2]), "+f"(d[3])
                 : "r"(a[0]), "r"(a[1]), "r"(a[2]), "r"(a[3]), "r"(b0), "r"(b1));
}
__device__ __forceinline__ void cpa16(uint32_t d, const void* s, int zfill) {
    asm volatile("cp.async.cg.shared.global [%0], [%1], 16, %2;" :: "r"(d), "l"(s), "r"(zfill));
}

// ---------------- elementwise fp32 -> bf16 hi/lo converters ----------------
__global__ void conv_x_kernel(const float* __restrict__ X, int total4) {
    int i = blockIdx.x * blockDim.x + threadIdx.x;
    if (i >= total4) return;
    float4 v = ld4(X + (size_t)i * 4);
    unsigned h0, l0, h1, l1;
    split2(v.x, v.y, h0, l0);
    split2(v.z, v.w, h1, l1);
    *reinterpret_cast<uint2*>(g_xh + (size_t)i * 4) = make_uint2(h0, h1);
    *reinterpret_cast<uint2*>(g_xl + (size_t)i * 4) = make_uint2(l0, l1);
}
__global__ void conv_w_kernel(const float* __restrict__ W, int total4) {
    int i = blockIdx.x * blockDim.x + threadIdx.x;
    if (i >= total4) return;
    float4 v = ld4(W + (size_t)i * 4);
    unsigned h0, l0, h1, l1;
    split2(v.x, v.y, h0, l0);
    split2(v.z, v.w, h1, l1);
    *reinterpret_cast<uint2*>(g_wh + (size_t)i * 4) = make_uint2(h0, h1);
    *reinterpret_cast<uint2*>(g_wl + (size_t)i * 4) = make_uint2(l0, l1);
}

// ======== HMMA split-bf16 GEMM (pre-converted operands): ========
// g_xw[row, z*NCOLS + col] = X[row,:]·W[z][:,col], A = g_xh/g_xl, B = g_wh/g_wl
template<int NCOLS, int KTOT>
__global__ void __launch_bounds__(256) mma_gemm(int ldY) {
    constexpr int BN = (NCOLS < 128) ? NCOLS : 128;
    constexpr int WN = BN / 2;
    constexpr int NF2 = WN / 16;
    constexpr int AST = 40;
    constexpr int BST = BN + 8;

    __shared__ __align__(16) __nv_bfloat16 Ah[128][AST];
    __shared__ __align__(16) __nv_bfloat16 Al[128][AST];
    __shared__ __align__(16) __nv_bfloat16 Bh[32][BST];
    __shared__ __align__(16) __nv_bfloat16 Bl[32][BST];

    const int tid = threadIdx.x;
    const int wid = tid >> 5, lane = tid & 31;
    const int wm = wid & 3, wn = wid >> 2;
    const int rowBase = blockIdx.x * 128;
    const int nbase = blockIdx.y * BN;
    const int z = blockIdx.z;
    const __nv_bfloat16* Wh = g_wh + (size_t)z * KTOT * NCOLS;
    const __nv_bfloat16* Wl = g_wl + (size_t)z * KTOT * NCOLS;

    float acc[2][WN / 8][4];
    #pragma unroll
    for (int i = 0; i < 2; i++)
        #pragma unroll
        for (int j = 0; j < WN / 8; j++)
            #pragma unroll
            for (int q = 0; q < 4; q++) acc[i][j][q] = 0.f;

    for (int k0 = 0; k0 < KTOT; k0 += 32) {
        // A: 128 rows x 32 k of bf16 -> 512 uint4 slots each for hi/lo
        #pragma unroll
        for (int i = 0; i < 2; i++) {
            int li = tid + i * 256;
            int row = li >> 2, c8 = (li & 3) * 8;
            int gr = rowBase + row;
            int zf = (gr < NN) ? 16 : 0;
            size_t goff = (size_t)gr * KTOT + k0 + c8;
            cpa16(smem_u32(&Ah[row][c8]), g_xh + goff, zf);
            cpa16(smem_u32(&Al[row][c8]), g_xl + goff, zf);
        }
        // B: 32 k-rows x BN cols -> (32*BN/8) uint4 slots each
        #pragma unroll
        for (int i = 0; i < BN / 64; i++) {
            int li = tid + i * 256;
            int row = li / (BN / 8), c8 = (li % (BN / 8)) * 8;
            size_t goff = (size_t)(k0 + row) * NCOLS + nbase + c8;
            cpa16(smem_u32(&Bh[row][c8]), Wh + goff, 16);
            cpa16(smem_u32(&Bl[row][c8]), Wl + goff, 16);
        }
        asm volatile("cp.async.commit_group;");
        asm volatile("cp.async.wait_group 0;");
        __syncthreads();
        // compute: 2 k16 steps
        #pragma unroll
        for (int ks = 0; ks < 2; ks++) {
            uint32_t ah[2][4], al[2][4];
            #pragma unroll
            for (int mf = 0; mf < 2; mf++) {
                int arow = wm * 32 + mf * 16 + (lane & 15);
                int acol = ks * 16 + ((lane >> 4) << 3);
                ldsm_x4(smem_u32(&Ah[arow][acol]), ah[mf][0], ah[mf][1], ah[mf][2], ah[mf][3]);
                ldsm_x4(smem_u32(&Al[arow][acol]), al[mf][0], al[mf][1], al[mf][2], al[mf][3]);
            }
            #pragma unroll
            for (int nf2 = 0; nf2 < NF2; nf2++) {
                int brow = ks * 16 + (lane & 15);
                int bcol = wn * WN + nf2 * 16 + ((lane >> 4) << 3);
                uint32_t bh[4], bl[4];
                ldsm_x4t(smem_u32(&Bh[brow][bcol]), bh[0], bh[1], bh[2], bh[3]);
                ldsm_x4t(smem_u32(&Bl[brow][bcol]), bl[0], bl[1], bl[2], bl[3]);
                #pragma unroll
                for (int half = 0; half < 2; half++) {
                    uint32_t bH0 = bh[half * 2], bH1 = bh[half * 2 + 1];
                    uint32_t bL0 = bl[half * 2], bL1 = bl[half * 2 + 1];
                    #pragma unroll
                    for (int mf = 0; mf < 2; mf++) {
                        float* d = acc[mf][nf2 * 2 + half];
                        mma_bf16(d, ah[mf], bH0, bH1);
                        mma_bf16(d, ah[mf], bL0, bL1);
                        mma_bf16(d, al[mf], bH0, bH1);
                    }
                }
            }
        }
        __syncthreads();
    }
    // epilogue
    const int colG = z * NCOLS + nbase + wn * WN + (lane & 3) * 2;
    #pragma unroll
    for (int mf = 0; mf < 2; mf++) {
        int r0 = rowBase + wm * 32 + mf * 16 + (lane >> 2);
        #pragma unroll
        for (int nf = 0; nf < WN / 8; nf++) {
            float* d = acc[mf][nf];
            int c = colG + nf * 8;
            if (r0 < NN)
                *reinterpret_cast<float2*>(g_xw + (size_t)r0 * ldY + c) = make_float2(d[0], d[1]);
            if (r0 + 8 < NN)
                *reinterpret_cast<float2*>(g_xw + (size_t)(r0 + 8) * ldY + c) = make_float2(d[2], d[3]);
        }
    }
}

// ---------------- ws[k][col] = sum_c W[r][k][h*C+c] * a_{src|dst}[h][c] ----------------
template<int H, int C>
__global__ void prep_ws_kernel(const float* __restrict__ W, const float* __restrict__ a_src,
                               const float* __restrict__ a_dst, int K) {
    int idx = blockIdx.x * blockDim.x + threadIdx.x;
    if (idx >= K * 64) return;
    int k = idx >> 6;
    int col = idx & 63;
    constexpr int RH = NR * H;
    float acc = 0.f;
    if (col < 2 * RH) {
        int isd = col >= RH;
        int rh = isd ? col - RH : col;
        int r = rh / H, h = rh % H;
        const float* a = isd ? a_dst : a_src;
        const float* wrow = W + ((size_t)r * K + k) * (H * C) + h * C;
        #pragma unroll 8
        for (int c = 0; c < C; c++) acc += wrow[c] * a[h * C + c];
    }
    g_ws[idx] = acc;
}

// ---------------- fp32 SGEMM (attention dots only): g_sd = X @ g_ws ----------------
template<int BN, int XH>
__global__ void __launch_bounds__(256) gemm_dots(const float* __restrict__ Xp, int K) {
    constexpr int BM = 128, BK = 16;
    constexpr int TN = BN / 16;
    const float* X = XH ? (const float*)g_h : Xp;
    const float* W = (const float*)g_ws;
    float* Y = (float*)g_sd;
    __shared__ float As[BK][BM];
    __shared__ float Bs[BK][BN];
    const int tid = threadIdx.x;
    const int tx = tid & 15, ty = tid >> 4;
    const int rowBase = blockIdx.x * BM;

    float acc[8][TN];
    #pragma unroll
    for (int i = 0; i < 8; i++)
        #pragma unroll
        for (int j = 0; j < TN; j++) acc[i][j] = 0.f;

    for (int k0 = 0; k0 < K; k0 += BK) {
        #pragma unroll
        for (int i = 0; i < 2; i++) {
            int idx = tid + i * 256;
            int ar = idx >> 2;
            int ac = (idx & 3) << 2;
            int gr = rowBase + ar;
            float4 v = make_float4(0.f, 0.f, 0.f, 0.f);
            if (gr < NN) v = ld4(X + (size_t)gr * K + k0 + ac);
            As[ac + 0][ar] = v.x; As[ac + 1][ar] = v.y;
            As[ac + 2][ar] = v.z; As[ac + 3][ar] = v.w;
        }
        if (tid < BK * BN / 4) {
            int br = tid / (BN / 4);
            int bc = (tid % (BN / 4)) << 2;
            st4(&Bs[br][bc], ld4(W + (size_t)(k0 + br) * 64 + bc));
        }
        __syncthreads();
        #pragma unroll
        for (int kk = 0; kk < BK; kk++) {
            float av[8], bv[TN];
            float4 a0 = *reinterpret_cast<const float4*>(&As[kk][ty * 4]);
            float4 a1 = *reinterpret_cast<const float4*>(&As[kk][64 + ty * 4]);
            av[0] = a0.x; av[1] = a0.y; av[2] = a0.z; av[3] = a0.w;
            av[4] = a1.x; av[5] = a1.y; av[6] = a1.z; av[7] = a1.w;
            float4 b0 = *reinterpret_cast<const float4*>(&Bs[kk][tx * 4]);
            bv[0] = b0.x; bv[1] = b0.y; bv[2] = b0.z; bv[3] = b0.w;
            #pragma unroll
            for (int i = 0; i < 8; i++)
                #pragma unroll
                for (int j = 0; j < TN; j++) acc[i][j] = fmaf(av[i], bv[j], acc[i][j]);
        }
        __syncthreads();
    }
    #pragma unroll
    for (int i = 0; i < 8; i++) {
        int lr = (i < 4) ? (ty * 4 + i) : (64 + ty * 4 + (i - 4));
        int gr = rowBase + lr;
        if (gr >= NN) continue;
        st4(Y + (size_t)gr * 64 + tx * 4, make_float4(acc[i][0], acc[i][1], acc[i][2], acc[i][3]));
    }
}

// ---------------- zero asum + accum in one pass ----------------
template<int H, int M>
__global__ void zero_soft_accum() {
    int i = blockIdx.x * blockDim.x + threadIdx.x;
    constexpr int NA = NN * H / 4;
    constexpr int NB = NN * M / 4;
    float4 zz = make_float4(0.f, 0.f, 0.f, 0.f);
    if (i < NA) st4((float*)g_asum + (size_t)i * 4, zz);
    else if (i < NA + NB) st4((float*)g_accum + (size_t)(i - NA) * 4, zz);
}

// ---------------- edge: logit -> leaky -> exp -> denom (no max shift; shift-invariant) ----------------
template<int H>
__global__ void edge_exp_kernel(const int* __restrict__ ei,
                                const int* __restrict__ et,
                                const float* __restrict__ arel) {
    int e = blockIdx.x * blockDim.x + threadIdx.x;
    if (e >= NE) return;
    int src = ei[e], dst = ei[NE + e], r = et[e];
    if constexpr (H == 4) {
        float4 s = ld4(g_sd + src * 64 + r * 4);
        float4 d = ld4(g_sd + dst * 64 + 32 + r * 4);
        float4 a = ld4(arel + r * 4);
        float4 v;
        v.x = s.x + d.x + a.x; v.y = s.y + d.y + a.y;
        v.z = s.z + d.z + a.z; v.w = s.w + d.w + a.w;
        v.x = v.x > 0.f ? v.x : 0.2f * v.x;
        v.y = v.y > 0.f ? v.y : 0.2f * v.y;
        v.z = v.z > 0.f ? v.z : 0.2f * v.z;
        v.w = v.w > 0.f ? v.w : 0.2f * v.w;
        float4 ex = make_float4(expf(v.x), expf(v.y), expf(v.z), expf(v.w));
        st4(g_alpha + (size_t)e * 4, ex);
        atomicAdd(reinterpret_cast<float4*>(g_asum + dst * 4), ex);
    } else {
        float v = g_sd[src * 64 + r] + g_sd[dst * 64 + 8 + r] + arel[r];
        v = v > 0.f ? v : 0.2f * v;
        float ex = expf(v);
        g_alpha[e] = ex;
        atomicAdd(&g_asum[dst], ex);
    }
}

// ---------------- weighted message aggregation (warp per edge) ----------------
template<int M, int H>
__global__ void agg_kernel(const int* __restrict__ ei, const int* __restrict__ et) {
    int gw = (blockIdx.x * blockDim.x + threadIdx.x) >> 5;
    int lane = threadIdx.x & 31;
    if (gw >= NE) return;
    int src = ei[gw], dst = ei[NE + gw], r = et[gw];
    const float* xp = g_xw + ((size_t)src * NR + r) * M;
    float* op = g_accum + (size_t)dst * M;
    if constexpr (H == 4) {
        float4 ex = ld4(g_alpha + (size_t)gw * 4);
        float4 den = ld4(g_asum + dst * 4);
        float w0 = ex.x / den.x, w1 = ex.y / den.y, w2 = ex.z / den.z, w3 = ex.w / den.w;
        float sA = (lane < 16) ? w0 : w1;
        float sB = (lane < 16) ? w2 : w3;
        float4 v0 = ld4(xp + lane * 4);
        float4 v1 = ld4(xp + 128 + lane * 4);
        v0.x *= sA; v0.y *= sA; v0.z *= sA; v0.w *= sA;
        v1.x *= sB; v1.y *= sB; v1.z *= sB; v1.w *= sB;
        atomicAdd(reinterpret_cast<float4*>(op + lane * 4), v0);
        atomicAdd(reinterpret_cast<float4*>(op + 128 + lane * 4), v1);
    } else {
        float w = g_alpha[gw] / g_asum[dst];
        if (lane < 16) {
            float4 v = ld4(xp + lane * 4);
            v.x *= w; v.y *= w; v.z *= w; v.w *= w;
            atomicAdd(reinterpret_cast<float4*>(op + lane * 4), v);
        }
    }
}

// ---------------- bias + layernorm + elu + bf16 hi/lo export (warp per node) ----------------
__global__ void ln_elu_kernel(const float* __restrict__ bias, const float* __restrict__ gam,
                              const float* __restrict__ bet) {
    int n = (blockIdx.x * blockDim.x + threadIdx.x) >> 5;
    int lane = threadIdx.x & 31;
    if (n >= NN) return;
    const float* ap = g_accum + (size_t)n * 256;
    int c0 = lane * 4, c1 = 128 + lane * 4;
    float4 x0 = ld4(ap + c0), x1 = ld4(ap + c1);
    float4 b0 = ld4(bias + c0), b1 = ld4(bias + c1);
    x0.x += b0.x; x0.y += b0.y; x0.z += b0.z; x0.w += b0.w;
    x1.x += b1.x; x1.y += b1.y; x1.z += b1.z; x1.w += b1.w;
    float sum = x0.x + x0.y + x0.z + x0.w + x1.x + x1.y + x1.z + x1.w;
    float sq = x0.x * x0.x + x0.y * x0.y + x0.z * x0.z + x0.w * x0.w
             + x1.x * x1.x + x1.y * x1.y + x1.z * x1.z + x1.w * x1.w;
    #pragma unroll
    for (int o = 16; o; o >>= 1) {
        sum += __shfl_xor_sync(0xffffffffu, sum, o);
        sq  += __shfl_xor_sync(0xffffffffu, sq, o);
    }
    float mean = sum * (1.f / 256.f);
    float var = sq * (1.f / 256.f) - mean * mean;
    float rstd = rsqrtf(var + 1e-5f);
    float4 g0 = ld4(gam + c0), g1 = ld4(gam + c1);
    float4 e0 = ld4(bet + c0), e1 = ld4(bet + c1);
    float4 y0, y1;
    y0.x = (x0.x - mean) * rstd * g0.x + e0.x;
    y0.y = (x0.y - mean) * rstd * g0.y + e0.y;
    y0.z = (x0.z - mean) * rstd * g0.z + e0.z;
    y0.w = (x0.w - mean) * rstd * g0.w + e0.w;
    y1.x = (x1.x - mean) * rstd * g1.x + e1.x;
    y1.y = (x1.y - mean) * rstd * g1.y + e1.y;
    y1.z = (x1.z - mean) * rstd * g1.z + e1.z;
    y1.w = (x1.w - mean) * rstd * g1.w + e1.w;
    y0.x = y0.x > 0.f ? y0.x : expm1f(y0.x);
    y0.y = y0.y > 0.f ? y0.y : expm1f(y0.y);
    y0.z = y0.z > 0.f ? y0.z : expm1f(y0.z);
    y0.w = y0.w > 0.f ? y0.w : expm1f(y0.w);
    y1.x = y1.x > 0.f ? y1.x : expm1f(y1.x);
    y1.y = y1.y > 0.f ? y1.y : expm1f(y1.y);
    y1.z = y1.z > 0.f ? y1.z : expm1f(y1.z);
    y1.w = y1.w > 0.f ? y1.w : expm1f(y1.w);
    float* hp = g_h + (size_t)n * 256;
    st4(hp + c0, y0);
    st4(hp + c1, y1);
    // fused bf16 hi/lo export for the next layer's MMA A operand
    unsigned h0, l0, h1, l1;
    split2(y0.x, y0.y, h0, l0);
    split2(y0.z, y0.w, h1, l1);
    *reinterpret_cast<uint2*>(g_xh + (size_t)n * 256 + c0) = make_uint2(h0, h1);
    *reinterpret_cast<uint2*>(g_xl + (size_t)n * 256 + c0) = make_uint2(l0, l1);
    split2(y1.x, y1.y, h0, l0);
    split2(y1.z, y1.w, h1, l1);
    *reinterpret_cast<uint2*>(g_xh + (size_t)n * 256 + c1) = make_uint2(h0, h1);
    *reinterpret_cast<uint2*>(g_xl + (size_t)n * 256 + c1) = make_uint2(l0, l1);
}

__global__ void final_bias_kernel(const float* __restrict__ bi, float* __restrict__ out) {
    int i = blockIdx.x * blockDim.x + threadIdx.x;
    if (i < NN * 64) out[i] = g_accum[i] + bi[i & 63];
}

// ---------------- orchestration (pure kernel launches) ----------------
extern "C" void kernel_launch(void* const* d_in, const int* in_sizes, int n_in,
                              void* d_out, int out_size) {
    (void)in_sizes; (void)n_in; (void)out_size;
    const float* x  = (const float*)d_in[0];
    const int* ei   = (const int*)d_in[1];
    const int* et   = (const int*)d_in[2];
    const float* W0 = (const float*)d_in[3];
    const float* as0 = (const float*)d_in[4];
    const float* ad0 = (const float*)d_in[5];
    const float* ar0 = (const float*)d_in[6];
    const float* bi0 = (const float*)d_in[7];
    const float* W1 = (const float*)d_in[8];
    const float* as1 = (const float*)d_in[9];
    const float* ad1 = (const float*)d_in[10];
    const float* ar1 = (const float*)d_in[11];
    const float* bi1 = (const float*)d_in[12];
    const float* W2 = (const float*)d_in[13];
    const float* as2 = (const float*)d_in[14];
    const float* ad2 = (const float*)d_in[15];
    const float* ar2 = (const float*)d_in[16];
    const float* bi2 = (const float*)d_in[17];
    const float* g0 = (const float*)d_in[18];
    const float* be0 = (const float*)d_in[19];
    const float* g1 = (const float*)d_in[20];
    const float* be1 = (const float*)d_in[21];
    float* out = (float*)d_out;

    const int TB = 256;
    const int NT = (NN + 127) / 128;
    dim3 gTC2(NT, 2, 8);
    dim3 gTC1(NT, 1, 8);
    int ge = (NE + TB - 1) / TB;
    int gw = (NE * 32 + TB - 1) / TB;
    int gn = (NN * 32 + TB - 1) / TB;
    const int Z44 = (NN * 4 / 4 + NN * 256 / 4 + TB - 1) / TB;
    const int Z14 = (NN * 1 / 4 + NN * 64 / 4 + TB - 1) / TB;

    // ======== layer 0: in=128 -> [8 rel] x 256, H=4 ========
    conv_w_kernel<<<(NR * 128 * 256 / 4 + TB - 1) / TB, TB>>>(W0, NR * 128 * 256 / 4);
    conv_x_kernel<<<(NN * 128 / 4 + TB - 1) / TB, TB>>>(x, NN * 128 / 4);
    prep_ws_kernel<4, 64><<<(128 * 64 + TB - 1) / TB, TB>>>(W0, as0, ad0, 128);
    gemm_dots<64, 0><<<NT, TB>>>(x, 128);
    mma_gemm<256, 128><<<gTC2, TB>>>(2048);
    zero_soft_accum<4, 256><<<Z44, TB>>>();
    edge_exp_kernel<4><<<ge, TB>>>(ei, et, ar0);
    agg_kernel<256, 4><<<gw, TB>>>(ei, et);
    ln_elu_kernel<<<gn, TB>>>(bi0, g0, be0);

    // ======== layer 1: in=256 -> [8 rel] x 256, H=4 ========
    conv_w_kernel<<<(NR * 256 * 256 / 4 + TB - 1) / TB, TB>>>(W1, NR * 256 * 256 / 4);
    prep_ws_kernel<4, 64><<<(256 * 64 + TB - 1) / TB, TB>>>(W1, as1, ad1, 256);
    gemm_dots<64, 1><<<NT, TB>>>(nullptr, 256);
    mma_gemm<256, 256><<<gTC2, TB>>>(2048);
    zero_soft_accum<4, 256><<<Z44, TB>>>();
    edge_exp_kernel<4><<<ge, TB>>>(ei, et, ar1);
    agg_kernel<256, 4><<<gw, TB>>>(ei, et);
    ln_elu_kernel<<<gn, TB>>>(bi1, g1, be1);

    // ======== layer 2: in=256 -> [8 rel] x 64, H=1, no concat ========
    conv_w_kernel<<<(NR * 256 * 64 / 4 + TB - 1) / TB, TB>>>(W2, NR * 256 * 64 / 4);
    prep_ws_kernel<1, 64><<<(256 * 64 + TB - 1) / TB, TB>>>(W2, as2, ad2, 256);
    gemm_dots<64, 1><<<NT, TB>>>(nullptr, 256);
    mma_gemm<64, 256><<<gTC1, TB>>>(512);
    zero_soft_accum<1, 64><<<Z14, TB>>>();
    edge_exp_kernel<1><<<ge, TB>>>(ei, et, ar2);
    agg_kernel<64, 1><<<gw, TB>>>(ei, et);
    final_bias_kernel<<<(NN * 64 + TB - 1) / TB, TB>>>(bi2, out);
}